// round 3
// baseline (speedup 1.0000x reference)
#include <cuda_runtime.h>

// Problem constants
#define B 256
#define T 512
#define H 512
#define O 2

// d_out layout (floats): out, hidden, net_units, read_out_units
#define HID_OFF (B * O)
#define NET_OFF (HID_OFF + B * H)
#define RO_OFF  (NET_OFF + B * T * H)

#define KC   64    // K-chunk per smem stage
#define HPAD 18    // Hs row pad (conflict-free stores/reads for 16-wide)
#define WPAD 34    // Ws row pad

// ---------------------------------------------------------------------------
// Pre-pass: net[b,t,j] = input[b,t,:] . W_in[j,:] + b_in[j] + b_hh[j] + sigma*noise[b,t,j]
// The step kernel then only needs: h = relu(pre + h_prev @ W_hh^T), read/written in place.
// ---------------------------------------------------------------------------
__global__ __launch_bounds__(128) void pre_kernel(
    const float* __restrict__ input,   // [B,T,2]
    const float* __restrict__ sigma,   // [1]
    const float* __restrict__ noise,   // [B,T,H]
    const float* __restrict__ W_in,    // [H,2]
    const float* __restrict__ b_in,    // [H]
    const float* __restrict__ b_hh,    // [H]
    float*       __restrict__ net)     // [B,T,H]
{
    const int t = blockIdx.x;
    const int b = blockIdx.y;
    const int j = threadIdx.x * 4;
    const size_t base = ((size_t)b * T + t) * H + j;

    const float in0 = input[((size_t)b * T + t) * 2 + 0];
    const float in1 = input[((size_t)b * T + t) * 2 + 1];
    const float sn  = sigma[0];

    float4 nz = *(const float4*)(noise + base);
    float4 r;
    float* rp = &r.x;
    const float* nzp = &nz.x;
    #pragma unroll
    for (int i = 0; i < 4; i++) {
        const int jj = j + i;
        rp[i] = in0 * W_in[jj * 2 + 0] + in1 * W_in[jj * 2 + 1]
              + b_in[jj] + b_hh[jj] + sn * nzp[i];
    }
    *(float4*)(net + base) = r;
}

// ---------------------------------------------------------------------------
// One recurrence step. Tile: 16 batch rows x 32 output cols, 128 threads.
// Grid (H/32, B/16) = (16,16) = 256 CTAs -> 2 co-resident CTAs on most SMs.
// Software pipeline: registers prefetch chunk i+1 while computing chunk i.
// ---------------------------------------------------------------------------
__global__ __launch_bounds__(128) void rnn_step_kernel(
    const float* __restrict__ W_hh,    // [H,H]
    float*       __restrict__ net,     // [B,T,H] (pre written by pre_kernel at [.,t,.])
    int t)
{
    __shared__ float Hs[KC][HPAD];   // Hs[k][m] = h_prev[b0+m][k0+k]
    __shared__ float Ws[KC][WPAD];   // Ws[k][n] = W_hh[j0+n][k0+k]

    const int j0  = blockIdx.x * 32;
    const int b0  = blockIdx.y * 16;
    const int tid = threadIdx.x;
    const int tm  = tid >> 3;   // 0..15  output row
    const int tn  = tid & 7;    // 0..7   -> 4 output cols

    float acc0 = 0.f, acc1 = 0.f, acc2 = 0.f, acc3 = 0.f;

    if (t > 0) {
        // Loader mapping (conflict-free smem stores):
        //   H tile: row = tid&15, k-offset = (tid>>4)*8  (2 float4 / thread)
        //   W tile: row = tid&31, k-offset = (tid>>5)*16 (4 float4 / thread)
        const int hrow = tid & 15;
        const int hk   = (tid >> 4) * 8;
        const int wrow = tid & 31;
        const int wk   = (tid >> 5) * 16;

        const float* hsrc = net  + ((size_t)(b0 + hrow) * T + (size_t)(t - 1)) * H + hk;
        const float* wsrc = W_hh + (size_t)(j0 + wrow) * H + wk;

        // Prefetch chunk 0
        float4 h0 = *(const float4*)(hsrc + 0);
        float4 h1 = *(const float4*)(hsrc + 4);
        float4 w0 = *(const float4*)(wsrc + 0);
        float4 w1 = *(const float4*)(wsrc + 4);
        float4 w2 = *(const float4*)(wsrc + 8);
        float4 w3 = *(const float4*)(wsrc + 12);

        for (int k0 = 0; k0 < H; k0 += KC) {
            // Stage prefetched chunk into smem
            Hs[hk + 0][hrow] = h0.x; Hs[hk + 1][hrow] = h0.y;
            Hs[hk + 2][hrow] = h0.z; Hs[hk + 3][hrow] = h0.w;
            Hs[hk + 4][hrow] = h1.x; Hs[hk + 5][hrow] = h1.y;
            Hs[hk + 6][hrow] = h1.z; Hs[hk + 7][hrow] = h1.w;
            Ws[wk +  0][wrow] = w0.x; Ws[wk +  1][wrow] = w0.y;
            Ws[wk +  2][wrow] = w0.z; Ws[wk +  3][wrow] = w0.w;
            Ws[wk +  4][wrow] = w1.x; Ws[wk +  5][wrow] = w1.y;
            Ws[wk +  6][wrow] = w1.z; Ws[wk +  7][wrow] = w1.w;
            Ws[wk +  8][wrow] = w2.x; Ws[wk +  9][wrow] = w2.y;
            Ws[wk + 10][wrow] = w2.z; Ws[wk + 11][wrow] = w2.w;
            Ws[wk + 12][wrow] = w3.x; Ws[wk + 13][wrow] = w3.y;
            Ws[wk + 14][wrow] = w3.z; Ws[wk + 15][wrow] = w3.w;
            __syncthreads();

            // Issue global loads for the next chunk; latency overlaps the FFMA loop
            const int kn = k0 + KC;
            if (kn < H) {
                h0 = *(const float4*)(hsrc + kn + 0);
                h1 = *(const float4*)(hsrc + kn + 4);
                w0 = *(const float4*)(wsrc + kn + 0);
                w1 = *(const float4*)(wsrc + kn + 4);
                w2 = *(const float4*)(wsrc + kn + 8);
                w3 = *(const float4*)(wsrc + kn + 12);
            }

            #pragma unroll
            for (int k = 0; k < KC; k++) {
                const float  h   = Hs[k][tm];
                const float2 wa  = *(const float2*)&Ws[k][tn * 4 + 0];
                const float2 wb  = *(const float2*)&Ws[k][tn * 4 + 2];
                acc0 += h * wa.x;
                acc1 += h * wa.y;
                acc2 += h * wb.x;
                acc3 += h * wb.y;
            }
            __syncthreads();   // protect smem before next stage's stores
        }
    }

    // Epilogue: h = relu(acc + pre), in place at net[b, t, j]
    float* dst = net + ((size_t)(b0 + tm) * T + t) * H + j0 + tn * 4;
    float4 pre = *(const float4*)dst;
    float4 r;
    r.x = fmaxf(acc0 + pre.x, 0.f);
    r.y = fmaxf(acc1 + pre.y, 0.f);
    r.z = fmaxf(acc2 + pre.z, 0.f);
    r.w = fmaxf(acc3 + pre.w, 0.f);
    *(float4*)dst = r;
}

// ---------------------------------------------------------------------------
// Readout: ro[b,t,o] = net[b,t,:] . W_fc[o,:] + b_fc[o]
// Also: out = ro[:, T-1, :], hidden = net[:, T-1, :]
// ---------------------------------------------------------------------------
__global__ __launch_bounds__(256) void readout_kernel(
    const float* __restrict__ net,     // [B,T,H]
    const float* __restrict__ W_fc,    // [O,H]
    const float* __restrict__ b_fc,    // [O]
    float*       __restrict__ ro,      // [B,T,O]
    float*       __restrict__ out,     // [B,O]
    float*       __restrict__ hidden)  // [B,H]
{
    __shared__ float4 w0s[H / 4];
    __shared__ float4 w1s[H / 4];
    const int tid = threadIdx.x;
    if (tid < H / 4)            w0s[tid]         = ((const float4*)W_fc)[tid];
    else if (tid < 2 * (H / 4)) w1s[tid - H / 4] = ((const float4*)(W_fc + H))[tid - H / 4];
    __syncthreads();

    const int warp = tid >> 5, lane = tid & 31;
    const int bt = blockIdx.x * 8 + warp;          // 0 .. B*T-1
    const int b = bt / T, t = bt % T;

    const float4* row = (const float4*)(net + (size_t)bt * H);
    float a0 = 0.f, a1 = 0.f;
    float4 vals[4];
    #pragma unroll
    for (int i = 0; i < 4; i++) {
        float4 v  = row[lane + 32 * i];
        float4 w0 = w0s[lane + 32 * i];
        float4 w1 = w1s[lane + 32 * i];
        vals[i] = v;
        a0 += v.x * w0.x + v.y * w0.y + v.z * w0.z + v.w * w0.w;
        a1 += v.x * w1.x + v.y * w1.y + v.z * w1.z + v.w * w1.w;
    }
    #pragma unroll
    for (int s = 16; s > 0; s >>= 1) {
        a0 += __shfl_xor_sync(0xFFFFFFFFu, a0, s);
        a1 += __shfl_xor_sync(0xFFFFFFFFu, a1, s);
    }
    if (lane == 0) {
        ro[(size_t)bt * 2 + 0] = a0 + b_fc[0];
        ro[(size_t)bt * 2 + 1] = a1 + b_fc[1];
    }
    if (t == T - 1) {
        if (lane == 0) {
            out[b * 2 + 0] = a0 + b_fc[0];
            out[b * 2 + 1] = a1 + b_fc[1];
        }
        float4* hid = (float4*)(hidden + (size_t)b * H);
        #pragma unroll
        for (int i = 0; i < 4; i++) hid[lane + 32 * i] = vals[i];
    }
}

extern "C" void kernel_launch(void* const* d_in, const int* in_sizes, int n_in,
                              void* d_out, int out_size)
{
    const float* input = (const float*)d_in[0];
    const float* sigma = (const float*)d_in[1];
    const float* noise = (const float*)d_in[2];
    const float* W_in  = (const float*)d_in[3];
    const float* b_in  = (const float*)d_in[4];
    const float* W_hh  = (const float*)d_in[5];
    const float* b_hh  = (const float*)d_in[6];
    const float* W_fc  = (const float*)d_in[7];
    const float* b_fc  = (const float*)d_in[8];

    float* out    = (float*)d_out;
    float* hidden = out + HID_OFF;
    float* net    = out + NET_OFF;
    float* ro     = out + RO_OFF;

    // Fold input projection + biases + noise into net[b,t,:]
    {
        dim3 g(T, B);
        pre_kernel<<<g, 128>>>(input, sigma, noise, W_in, b_in, b_hh, net);
    }

    // 512 sequential recurrence steps
    {
        dim3 g(H / 32, B / 16);   // 16 x 16 = 256 CTAs
        for (int t = 0; t < T; t++) {
            rnn_step_kernel<<<g, 128>>>(W_hh, net, t);
        }
    }

    readout_kernel<<<(B * T) / 8, 256>>>(net, W_fc, b_fc, ro, out, hidden);
}